// round 5
// baseline (speedup 1.0000x reference)
#include <cuda_runtime.h>
#include <math.h>

#define S4     4
#define D4     1024
#define KDIM   4096      // S*D
#define RROWS  24        // 16 res + 4 pre + 4 post
#define MAXNT  8192      // B*T
#define CK     512       // k per chunk
#define NCH    (KDIM/CK) // 8
#define TPB    16        // tokens per block (dots)

// -------- scratch (no cudaMalloc allowed) --------
__device__ float g_wg  [RROWS * KDIM];   // w * (1+gamma), row-major [r][k]
__device__ float g_dots[MAXNT * RROWS];  // raw dots per token
__device__ float g_ssq [MAXNT];          // sum of squares per token
__device__ float g_H   [MAXNT * RROWS];  // Hres[16], Hpre[4], Hpost[4]

typedef unsigned long long u64;

__device__ __forceinline__ u64 fma2(u64 a, u64 b, u64 c) {
    u64 d;
    asm("fma.rn.f32x2 %0, %1, %2, %3;" : "=l"(d) : "l"(a), "l"(b), "l"(c));
    return d;
}
__device__ __forceinline__ u64 add2(u64 a, u64 b) {
    u64 d;
    asm("add.rn.f32x2 %0, %1, %2;" : "=l"(d) : "l"(a), "l"(b));
    return d;
}
__device__ __forceinline__ float f2sum(u64 a) {
    float lo, hi;
    asm("mov.b64 {%0,%1}, %2;" : "=f"(lo), "=f"(hi) : "l"(a));
    return lo + hi;
}
__device__ __forceinline__ void cpasync16(void* dst_smem, const void* src) {
    unsigned d = (unsigned)__cvta_generic_to_shared(dst_smem);
    asm volatile("cp.async.cg.shared.global [%0], [%1], 16;" :: "r"(d), "l"(src));
}
// hardware MUFU.EX2 / MUFU.LG2
__device__ __forceinline__ float ex2f(float x) {
    float r;
    asm("ex2.approx.f32 %0, %1;" : "=f"(r) : "f"(x));
    return r;
}
__device__ __forceinline__ float lg2f(float x) {
    float r;
    asm("lg2.approx.f32 %0, %1;" : "=f"(r) : "f"(x));
    return r;
}

// ============================================================
// K0: fold gamma into concatenated weight matrix
// ============================================================
__global__ void prep_kernel(const float* __restrict__ w_res,
                            const float* __restrict__ w_pre,
                            const float* __restrict__ w_post,
                            const float* __restrict__ gamma) {
    int idx = blockIdx.x * blockDim.x + threadIdx.x;
    if (idx >= RROWS * KDIM) return;
    int r = idx >> 12;          // / 4096
    int k = idx & (KDIM - 1);
    float w;
    if (r < 16)      w = w_res [r * KDIM + k];
    else if (r < 20) w = w_pre [(r - 16) * KDIM + k];
    else             w = w_post[(r - 20) * KDIM + k];
    g_wg[idx] = w * (1.0f + gamma[k]);
}

// ============================================================
// K1: per-token sumsq + 24 raw dots.  k-pair f32x2 scheme.
// Block = 16 tokens, 256 threads (8 warps = 4 warp-pairs).
// Warp-pair p owns tokens tok0..tok0+3; half 0 -> rows 0..11 (+ssq),
// half 1 -> rows 12..23. x: LDG.128 straight to registers (k-pairs are
// the natural layout), one superstep (128 k) of prefetch. w: smem,
// double-buffered cp.async; LDS.128 yields two u64 k-pair operands
// directly -- zero packing MOVs.
// ============================================================
__global__ void __launch_bounds__(256, 1)
dots_kernel(const float* __restrict__ x) {
    extern __shared__ __align__(16) float sw[];   // [2][RROWS*CK]

    const int tid  = threadIdx.x;
    const int lane = tid & 31;
    const int warp = tid >> 5;
    const int pair = warp >> 1;        // 0..3
    const int half = warp & 1;         // row half
    const int tok0 = blockIdx.x * TPB + pair * 4;
    const float* xb = x + (size_t)tok0 * KDIM;

    u64 acc[12][4];
#pragma unroll
    for (int r = 0; r < 12; ++r)
#pragma unroll
        for (int t = 0; t < 4; ++t) acc[r][t] = 0ull;
    u64 ssq[4] = {0ull, 0ull, 0ull, 0ull};

    // ---- stage chunk 0 (24*512 floats = 3072 float4, 12/thread) ----
#pragma unroll
    for (int j = 0; j < 12; ++j) {
        int f = tid + 256 * j;
        int row = f >> 7, col4 = f & 127;
        cpasync16(sw + row * CK + col4 * 4,
                  g_wg + row * KDIM + col4 * 4);
    }
    asm volatile("cp.async.commit_group;");

    // ---- prefetch first x superstep ----
    const int klane = lane * 4;
    ulonglong2 xc[4], xn[4];
#pragma unroll
    for (int t = 0; t < 4; ++t)
        xc[t] = *(const ulonglong2*)(xb + (size_t)t * KDIM + klane);

    asm volatile("cp.async.wait_group 0;" ::: "memory");
    __syncthreads();

    int gk = 0;                                     // global k of current ss
    for (int c = 0; c < NCH; ++c) {
        const float* swb = sw + (c & 1) * (RROWS * CK);

        if (c + 1 < NCH) {                          // stage next w chunk
            float* swn = sw + ((c + 1) & 1) * (RROWS * CK);
#pragma unroll
            for (int j = 0; j < 12; ++j) {
                int f = tid + 256 * j;
                int row = f >> 7, col4 = f & 127;
                cpasync16(swn + row * CK + col4 * 4,
                          g_wg + row * KDIM + (c + 1) * CK + col4 * 4);
            }
            asm volatile("cp.async.commit_group;");
        }

#pragma unroll
        for (int ss = 0; ss < 4; ++ss) {
            const int gn = gk + 128;
            if (gn < KDIM) {                        // prefetch next x ss
#pragma unroll
                for (int t = 0; t < 4; ++t)
                    xn[t] = *(const ulonglong2*)(xb + (size_t)t * KDIM
                                                 + gn + klane);
            }
            const float* wb = swb + (half * 12) * CK + ss * 128 + klane;
#pragma unroll
            for (int r = 0; r < 12; ++r) {
                ulonglong2 wv = *(const ulonglong2*)(wb + r * CK);
#pragma unroll
                for (int t = 0; t < 4; ++t) {
                    acc[r][t] = fma2(wv.x, xc[t].x, acc[r][t]);
                    acc[r][t] = fma2(wv.y, xc[t].y, acc[r][t]);
                }
            }
            if (half == 0) {
#pragma unroll
                for (int t = 0; t < 4; ++t) {
                    ssq[t] = fma2(xc[t].x, xc[t].x, ssq[t]);
                    ssq[t] = fma2(xc[t].y, xc[t].y, ssq[t]);
                }
            }
#pragma unroll
            for (int t = 0; t < 4; ++t) xc[t] = xn[t];
            gk = gn;
        }

        if (c + 1 < NCH)
            asm volatile("cp.async.wait_group 0;" ::: "memory");
        __syncthreads();
    }

    // ---- reduce across lanes and write ----
#pragma unroll
    for (int r = 0; r < 12; ++r) {
#pragma unroll
        for (int t = 0; t < 4; ++t) {
            u64 a = acc[r][t];
            a = add2(a, __shfl_down_sync(0xffffffffu, a, 16));
            a = add2(a, __shfl_down_sync(0xffffffffu, a, 8));
            a = add2(a, __shfl_down_sync(0xffffffffu, a, 4));
            a = add2(a, __shfl_down_sync(0xffffffffu, a, 2));
            a = add2(a, __shfl_down_sync(0xffffffffu, a, 1));
            if (lane == 0)
                g_dots[(size_t)(tok0 + t) * RROWS + half * 12 + r] = f2sum(a);
        }
    }
    if (half == 0) {
#pragma unroll
        for (int t = 0; t < 4; ++t) {
            u64 a = ssq[t];
            a = add2(a, __shfl_down_sync(0xffffffffu, a, 16));
            a = add2(a, __shfl_down_sync(0xffffffffu, a, 8));
            a = add2(a, __shfl_down_sync(0xffffffffu, a, 4));
            a = add2(a, __shfl_down_sync(0xffffffffu, a, 2));
            a = add2(a, __shfl_down_sync(0xffffffffu, a, 1));
            if (lane == 0) g_ssq[tok0 + t] = f2sum(a);
        }
    }
}

// ============================================================
// K2: per-token heads (sinkhorn + softmax + sigmoid), base-2 fast math
// ============================================================
#define LOG2E 1.4426950408889634f

__device__ __forceinline__ float lse4_2(float a, float b, float c, float d) {
    // base-2 log-sum-exp
    float m = fmaxf(fmaxf(a, b), fmaxf(c, d));
    float s = ex2f(a - m) + ex2f(b - m) + ex2f(c - m) + ex2f(d - m);
    return m + lg2f(s);
}

__global__ void heads_kernel(const float* __restrict__ beta_res,
                             const float* __restrict__ beta_pre,
                             const float* __restrict__ beta_post,
                             const float* __restrict__ alpha_res,
                             const float* __restrict__ alpha_pre,
                             const float* __restrict__ alpha_post,
                             int nt) {
    int tok = blockIdx.x * blockDim.x + threadIdx.x;
    if (tok >= nt) return;

    float rstd = 64.0f / fmaxf(sqrtf(g_ssq[tok]), 1e-12f);
    const float* dp = g_dots + (size_t)tok * RROWS;
    float ar = alpha_res[0]  * rstd;
    float ap = alpha_pre[0]  * rstd;
    float ao = alpha_post[0] * rstd;

    // Z2 = (Z / tau) * log2(e);  tau = 0.05
    float Z[16];
#pragma unroll
    for (int e = 0; e < 16; ++e)
        Z[e] = (beta_res[e] + ar * dp[e]) * (20.0f * LOG2E);

    float u[4] = {0.f, 0.f, 0.f, 0.f};
    float v[4] = {0.f, 0.f, 0.f, 0.f};
#pragma unroll 1
    for (int itn = 0; itn < 10; ++itn) {
#pragma unroll
        for (int i = 0; i < 4; ++i)
            u[i] = -lse4_2(Z[i*4+0] + v[0], Z[i*4+1] + v[1],
                           Z[i*4+2] + v[2], Z[i*4+3] + v[3]);
#pragma unroll
        for (int j = 0; j < 4; ++j)
            v[j] = -lse4_2(Z[0*4+j] + u[0], Z[1*4+j] + u[1],
                           Z[2*4+j] + u[2], Z[3*4+j] + u[3]);
    }

    float* hp = g_H + (size_t)tok * RROWS;
#pragma unroll
    for (int i = 0; i < 4; ++i)
#pragma unroll
        for (int j = 0; j < 4; ++j)
            hp[i*4+j] = ex2f(Z[i*4+j] + u[i] + v[j]);

    // H_pre = softmax (base-2)
    float p[4];
#pragma unroll
    for (int s = 0; s < 4; ++s)
        p[s] = (beta_pre[s] + ap * dp[16 + s]) * LOG2E;
    float m = fmaxf(fmaxf(p[0], p[1]), fmaxf(p[2], p[3]));
    float e0 = ex2f(p[0]-m), e1 = ex2f(p[1]-m);
    float e2 = ex2f(p[2]-m), e3 = ex2f(p[3]-m);
    float inv = 1.0f / (e0 + e1 + e2 + e3);
    hp[16] = e0*inv; hp[17] = e1*inv; hp[18] = e2*inv; hp[19] = e3*inv;

    // H_post = 2*sigmoid
#pragma unroll
    for (int s = 0; s < 4; ++s) {
        float q = beta_post[s] + ao * dp[20 + s];
        hp[20 + s] = 2.0f / (1.0f + ex2f(-q * LOG2E));
    }
}

// ============================================================
// K3: out[i,d] = sum_j Hres[i][j] x[j,d] + Hpost[i] * sum_s Hpre[s] x[s,d]
// ============================================================
__global__ void __launch_bounds__(256)
mix_kernel(const float* __restrict__ x, float* __restrict__ out) {
    const int tok = blockIdx.x;
    const float* xr = x   + (size_t)tok * KDIM;
    float*       yr = out + (size_t)tok * KDIM;
    const float* hp = g_H + (size_t)tok * RROWS;

    float hres[16], hpre[4], hpost[4];
#pragma unroll
    for (int e = 0; e < 16; ++e) hres[e] = __ldg(hp + e);
#pragma unroll
    for (int s = 0; s < 4; ++s)  hpre[s]  = __ldg(hp + 16 + s);
#pragma unroll
    for (int s = 0; s < 4; ++s)  hpost[s] = __ldg(hp + 20 + s);

    const int col = threadIdx.x * 4;
    float4 xj[4];
#pragma unroll
    for (int j = 0; j < 4; ++j)
        xj[j] = __ldcs((const float4*)(xr + j * D4 + col));

    float4 bin;
    bin.x = hpre[0]*xj[0].x + hpre[1]*xj[1].x + hpre[2]*xj[2].x + hpre[3]*xj[3].x;
    bin.y = hpre[0]*xj[0].y + hpre[1]*xj[1].y + hpre[2]*xj[2].y + hpre[3]*xj[3].y;
    bin.z = hpre[0]*xj[0].z + hpre[1]*xj[1].z + hpre[2]*xj[2].z + hpre[3]*xj[3].z;
    bin.w = hpre[0]*xj[0].w + hpre[1]*xj[1].w + hpre[2]*xj[2].w + hpre[3]*xj[3].w;

#pragma unroll
    for (int i = 0; i < 4; ++i) {
        float4 o;
        o.x = hpost[i]*bin.x; o.y = hpost[i]*bin.y;
        o.z = hpost[i]*bin.z; o.w = hpost[i]*bin.w;
#pragma unroll
        for (int j = 0; j < 4; ++j) {
            float h = hres[i*4 + j];
            o.x += h * xj[j].x; o.y += h * xj[j].y;
            o.z += h * xj[j].z; o.w += h * xj[j].w;
        }
        __stcs((float4*)(yr + i * D4 + col), o);
    }
}

// ============================================================
// launch
// ============================================================
extern "C" void kernel_launch(void* const* d_in, const int* in_sizes, int n_in,
                              void* d_out, int out_size) {
    const float* residuals  = (const float*)d_in[0];
    const float* gamma      = (const float*)d_in[1];
    const float* w_res      = (const float*)d_in[2];
    const float* w_pre      = (const float*)d_in[3];
    const float* w_post     = (const float*)d_in[4];
    const float* beta_res   = (const float*)d_in[5];
    const float* beta_pre   = (const float*)d_in[6];
    const float* beta_post  = (const float*)d_in[7];
    const float* alpha_res  = (const float*)d_in[8];
    const float* alpha_pre  = (const float*)d_in[9];
    const float* alpha_post = (const float*)d_in[10];

    const int nt = in_sizes[0] / KDIM;   // B*T tokens (8192)

    const int smem_bytes = 2 * RROWS * CK * 4;   // 96 KB
    static bool attr_set = false;
    if (!attr_set) {
        cudaFuncSetAttribute(dots_kernel,
                             cudaFuncAttributeMaxDynamicSharedMemorySize,
                             smem_bytes);
        attr_set = true;
    }

    prep_kernel<<<(RROWS * KDIM + 255) / 256, 256>>>(w_res, w_pre, w_post, gamma);
    dots_kernel<<<nt / TPB, 256, smem_bytes>>>(residuals);
    heads_kernel<<<(nt + 127) / 128, 128>>>(beta_res, beta_pre, beta_post,
                                            alpha_res, alpha_pre, alpha_post, nt);
    mix_kernel<<<nt, 256>>>(residuals, (float*)d_out);
}

// round 6
// speedup vs baseline: 1.4992x; 1.4992x over previous
#include <cuda_runtime.h>
#include <math.h>

#define D4     1024
#define KDIM   4096      // S*D
#define RROWS  24        // 16 res + 4 pre + 4 post
#define RP     12        // row pairs (r, r+12)
#define MAXNT  8192      // B*T
#define CK     512       // k per chunk
#define NCH    (KDIM/CK) // 8
#define TPB    32        // tokens per block (dots)

// -------- scratch (no cudaMalloc allowed) --------
typedef unsigned long long u64;
__device__ u64   g_w2  [RP * KDIM];      // (w_rp[k]*(1+g), w_rp+12[k]*(1+g))
__device__ float g_dots[MAXNT * RROWS];  // raw dots per token
__device__ float g_ssq [MAXNT];          // sum of squares per token
__device__ float g_H   [MAXNT * RROWS];  // Hres[16], Hpre[4], Hpost[4]

__device__ __forceinline__ u64 fma2(u64 a, u64 b, u64 c) {
    u64 d;
    asm("fma.rn.f32x2 %0, %1, %2, %3;" : "=l"(d) : "l"(a), "l"(b), "l"(c));
    return d;
}
__device__ __forceinline__ u64 add2(u64 a, u64 b) {
    u64 d;
    asm("add.rn.f32x2 %0, %1, %2;" : "=l"(d) : "l"(a), "l"(b));
    return d;
}
__device__ __forceinline__ u64 pack2(float lo, float hi) {
    u64 d;
    asm("mov.b64 %0, {%1, %2};" : "=l"(d) : "f"(lo), "f"(hi));
    return d;
}
__device__ __forceinline__ void unpack2(u64 a, float& lo, float& hi) {
    asm("mov.b64 {%0, %1}, %2;" : "=f"(lo), "=f"(hi) : "l"(a));
}
__device__ __forceinline__ void cpasync16(void* dst_smem, const void* src) {
    unsigned d = (unsigned)__cvta_generic_to_shared(dst_smem);
    asm volatile("cp.async.cg.shared.global [%0], [%1], 16;" :: "r"(d), "l"(src));
}
__device__ __forceinline__ float ex2f(float x) {
    float r;
    asm("ex2.approx.f32 %0, %1;" : "=f"(r) : "f"(x));
    return r;
}
__device__ __forceinline__ float lg2f(float x) {
    float r;
    asm("lg2.approx.f32 %0, %1;" : "=f"(r) : "f"(x));
    return r;
}

// ============================================================
// K0: fold gamma, pack row pairs (rp, rp+12) into u64
// ============================================================
__global__ void prep_kernel(const float* __restrict__ w_res,
                            const float* __restrict__ w_pre,
                            const float* __restrict__ w_post,
                            const float* __restrict__ gamma) {
    int idx = blockIdx.x * blockDim.x + threadIdx.x;
    if (idx >= RP * KDIM) return;
    int rp = idx >> 12;          // 0..11  (all in w_res)
    int k  = idx & (KDIM - 1);
    float g = 1.0f + gamma[k];
    float lo = w_res[rp * KDIM + k] * g;
    int rh = rp + 12;
    float hi;
    if (rh < 16)      hi = w_res [rh * KDIM + k];
    else if (rh < 20) hi = w_pre [(rh - 16) * KDIM + k];
    else              hi = w_post[(rh - 20) * KDIM + k];
    hi *= g;
    g_w2[idx] = pack2(lo, hi);
}

// ============================================================
// K1: per-token sumsq + 24 raw dots.  Row-pair f32x2 scheme.
// 256 threads, 8 warps, 32 tokens/block; warp w owns tokens 4w..4w+3
// and ALL 24 rows as 12 (r, r+12) f32x2 pairs.
// w2 and x both staged via cp.async, double-buffered (224 KB smem);
// x enters smem exactly once; prefetch distance = full 512-k chunk.
// ============================================================
__global__ void __launch_bounds__(256, 1)
dots_kernel(const float* __restrict__ x) {
    extern __shared__ __align__(16) char smem_raw[];
    u64*   sw2 = (u64*)smem_raw;                          // [2][RP*CK]
    float* sx  = (float*)(smem_raw + 2 * RP * CK * 8);    // [2][TPB*CK]

    const int tid  = threadIdx.x;
    const int lane = tid & 31;
    const int warp = tid >> 5;               // 0..7
    const int tok_blk = blockIdx.x * TPB;
    const int tok0    = tok_blk + warp * 4;

    u64 acc[RP][4];
#pragma unroll
    for (int rp = 0; rp < RP; ++rp)
#pragma unroll
        for (int t = 0; t < 4; ++t) acc[rp][t] = 0ull;
    float ssq[4] = {0.f, 0.f, 0.f, 0.f};

    // ---- stage chunk 0 into buf 0 ----
#pragma unroll
    for (int j = 0; j < 12; ++j) {           // w2: 12*512 u64 = 3072 x 16B
        int i = tid + 256 * j;
        int rp = i >> 8, kc2 = i & 255;
        cpasync16(sw2 + rp * CK + kc2 * 2,
                  g_w2 + rp * KDIM + kc2 * 2);
    }
#pragma unroll
    for (int j = 0; j < 16; ++j) {           // x: 32*512 f32 = 4096 x 16B
        int i = tid + 256 * j;
        int tok = i >> 7, kc = i & 127;
        cpasync16(sx + tok * CK + kc * 4,
                  x + (size_t)(tok_blk + tok) * KDIM + kc * 4);
    }
    asm volatile("cp.async.commit_group;");
    asm volatile("cp.async.wait_group 0;" ::: "memory");
    __syncthreads();

    for (int c = 0; c < NCH; ++c) {
        const int buf = c & 1;
        const u64*   sw2b = sw2 + buf * (RP * CK);
        const float* sxb  = sx  + buf * (TPB * CK);

        if (c + 1 < NCH) {                   // stage next chunk
            const int nbuf = buf ^ 1;
#pragma unroll
            for (int j = 0; j < 12; ++j) {
                int i = tid + 256 * j;
                int rp = i >> 8, kc2 = i & 255;
                cpasync16(sw2 + nbuf * (RP * CK) + rp * CK + kc2 * 2,
                          g_w2 + rp * KDIM + (c + 1) * CK + kc2 * 2);
            }
#pragma unroll
            for (int j = 0; j < 16; ++j) {
                int i = tid + 256 * j;
                int tok = i >> 7, kc = i & 127;
                cpasync16(sx + nbuf * (TPB * CK) + tok * CK + kc * 4,
                          x + (size_t)(tok_blk + tok) * KDIM
                            + (c + 1) * CK + kc * 4);
            }
            asm volatile("cp.async.commit_group;");
        }

        // ---- compute 8 steps of 64 k (2 k per lane) ----
#pragma unroll
        for (int it = 0; it < 8; ++it) {
            const int k0 = it * 64 + lane * 2;
            float2 xv[4];
            u64 xx0[4], xx1[4];
#pragma unroll
            for (int t = 0; t < 4; ++t) {
                xv[t] = *(const float2*)(sxb + (warp * 4 + t) * CK + k0);
                xx0[t] = pack2(xv[t].x, xv[t].x);
                xx1[t] = pack2(xv[t].y, xv[t].y);
            }
#pragma unroll
            for (int rp = 0; rp < RP; ++rp) {
                ulonglong2 wv = *(const ulonglong2*)(sw2b + rp * CK + k0);
#pragma unroll
                for (int t = 0; t < 4; ++t) {
                    acc[rp][t] = fma2(wv.x, xx0[t], acc[rp][t]);
                    acc[rp][t] = fma2(wv.y, xx1[t], acc[rp][t]);
                }
            }
#pragma unroll
            for (int t = 0; t < 4; ++t) {
                ssq[t] = fmaf(xv[t].x, xv[t].x, ssq[t]);
                ssq[t] = fmaf(xv[t].y, xv[t].y, ssq[t]);
            }
        }

        if (c + 1 < NCH)
            asm volatile("cp.async.wait_group 0;" ::: "memory");
        __syncthreads();
    }

    // ---- reduce across lanes and write ----
#pragma unroll
    for (int rp = 0; rp < RP; ++rp) {
#pragma unroll
        for (int t = 0; t < 4; ++t) {
            u64 a = acc[rp][t];
            a = add2(a, __shfl_down_sync(0xffffffffu, a, 16));
            a = add2(a, __shfl_down_sync(0xffffffffu, a, 8));
            a = add2(a, __shfl_down_sync(0xffffffffu, a, 4));
            a = add2(a, __shfl_down_sync(0xffffffffu, a, 2));
            a = add2(a, __shfl_down_sync(0xffffffffu, a, 1));
            if (lane == 0) {
                float lo, hi; unpack2(a, lo, hi);
                g_dots[(size_t)(tok0 + t) * RROWS + rp]      = lo;
                g_dots[(size_t)(tok0 + t) * RROWS + rp + 12] = hi;
            }
        }
    }
#pragma unroll
    for (int t = 0; t < 4; ++t) {
        float v = ssq[t];
        v += __shfl_down_sync(0xffffffffu, v, 16);
        v += __shfl_down_sync(0xffffffffu, v, 8);
        v += __shfl_down_sync(0xffffffffu, v, 4);
        v += __shfl_down_sync(0xffffffffu, v, 2);
        v += __shfl_down_sync(0xffffffffu, v, 1);
        if (lane == 0) g_ssq[tok0 + t] = v;
    }
}

// ============================================================
// K2: per-token heads (sinkhorn + softmax + sigmoid), base-2 MUFU
// ============================================================
#define LOG2E 1.4426950408889634f

__device__ __forceinline__ float lse4_2(float a, float b, float c, float d) {
    float m = fmaxf(fmaxf(a, b), fmaxf(c, d));
    float s = ex2f(a - m) + ex2f(b - m) + ex2f(c - m) + ex2f(d - m);
    return m + lg2f(s);
}

__global__ void heads_kernel(const float* __restrict__ beta_res,
                             const float* __restrict__ beta_pre,
                             const float* __restrict__ beta_post,
                             const float* __restrict__ alpha_res,
                             const float* __restrict__ alpha_pre,
                             const float* __restrict__ alpha_post,
                             int nt) {
    int tok = blockIdx.x * blockDim.x + threadIdx.x;
    if (tok >= nt) return;

    float rstd = 64.0f / fmaxf(sqrtf(g_ssq[tok]), 1e-12f);
    const float* dp = g_dots + (size_t)tok * RROWS;
    float ar = alpha_res[0]  * rstd;
    float ap = alpha_pre[0]  * rstd;
    float ao = alpha_post[0] * rstd;

    float Z[16];
#pragma unroll
    for (int e = 0; e < 16; ++e)
        Z[e] = (beta_res[e] + ar * dp[e]) * (20.0f * LOG2E);

    float u[4] = {0.f, 0.f, 0.f, 0.f};
    float v[4] = {0.f, 0.f, 0.f, 0.f};
#pragma unroll 1
    for (int itn = 0; itn < 10; ++itn) {
#pragma unroll
        for (int i = 0; i < 4; ++i)
            u[i] = -lse4_2(Z[i*4+0] + v[0], Z[i*4+1] + v[1],
                           Z[i*4+2] + v[2], Z[i*4+3] + v[3]);
#pragma unroll
        for (int j = 0; j < 4; ++j)
            v[j] = -lse4_2(Z[0*4+j] + u[0], Z[1*4+j] + u[1],
                           Z[2*4+j] + u[2], Z[3*4+j] + u[3]);
    }

    float* hp = g_H + (size_t)tok * RROWS;
#pragma unroll
    for (int i = 0; i < 4; ++i)
#pragma unroll
        for (int j = 0; j < 4; ++j)
            hp[i*4+j] = ex2f(Z[i*4+j] + u[i] + v[j]);

    float p[4];
#pragma unroll
    for (int s = 0; s < 4; ++s)
        p[s] = (beta_pre[s] + ap * dp[16 + s]) * LOG2E;
    float m = fmaxf(fmaxf(p[0], p[1]), fmaxf(p[2], p[3]));
    float e0 = ex2f(p[0]-m), e1 = ex2f(p[1]-m);
    float e2 = ex2f(p[2]-m), e3 = ex2f(p[3]-m);
    float inv = 1.0f / (e0 + e1 + e2 + e3);
    hp[16] = e0*inv; hp[17] = e1*inv; hp[18] = e2*inv; hp[19] = e3*inv;

#pragma unroll
    for (int s = 0; s < 4; ++s) {
        float q = beta_post[s] + ao * dp[20 + s];
        hp[20 + s] = 2.0f / (1.0f + ex2f(-q * LOG2E));
    }
}

// ============================================================
// K3: out[i,d] = sum_j Hres[i][j] x[j,d] + Hpost[i] * sum_s Hpre[s] x[s,d]
// ============================================================
__global__ void __launch_bounds__(256)
mix_kernel(const float* __restrict__ x, float* __restrict__ out) {
    const int tok = blockIdx.x;
    const float* xr = x   + (size_t)tok * KDIM;
    float*       yr = out + (size_t)tok * KDIM;
    const float* hp = g_H + (size_t)tok * RROWS;

    float hres[16], hpre[4], hpost[4];
#pragma unroll
    for (int e = 0; e < 16; ++e) hres[e] = __ldg(hp + e);
#pragma unroll
    for (int s = 0; s < 4; ++s)  hpre[s]  = __ldg(hp + 16 + s);
#pragma unroll
    for (int s = 0; s < 4; ++s)  hpost[s] = __ldg(hp + 20 + s);

    const int col = threadIdx.x * 4;
    float4 xj[4];
#pragma unroll
    for (int j = 0; j < 4; ++j)
        xj[j] = __ldcs((const float4*)(xr + j * D4 + col));

    float4 bin;
    bin.x = hpre[0]*xj[0].x + hpre[1]*xj[1].x + hpre[2]*xj[2].x + hpre[3]*xj[3].x;
    bin.y = hpre[0]*xj[0].y + hpre[1]*xj[1].y + hpre[2]*xj[2].y + hpre[3]*xj[3].y;
    bin.z = hpre[0]*xj[0].z + hpre[1]*xj[1].z + hpre[2]*xj[2].z + hpre[3]*xj[3].z;
    bin.w = hpre[0]*xj[0].w + hpre[1]*xj[1].w + hpre[2]*xj[2].w + hpre[3]*xj[3].w;

#pragma unroll
    for (int i = 0; i < 4; ++i) {
        float4 o;
        o.x = hpost[i]*bin.x; o.y = hpost[i]*bin.y;
        o.z = hpost[i]*bin.z; o.w = hpost[i]*bin.w;
#pragma unroll
        for (int j = 0; j < 4; ++j) {
            float h = hres[i*4 + j];
            o.x += h * xj[j].x; o.y += h * xj[j].y;
            o.z += h * xj[j].z; o.w += h * xj[j].w;
        }
        __stcs((float4*)(yr + i * D4 + col), o);
    }
}

// ============================================================
// launch
// ============================================================
extern "C" void kernel_launch(void* const* d_in, const int* in_sizes, int n_in,
                              void* d_out, int out_size) {
    const float* residuals  = (const float*)d_in[0];
    const float* gamma      = (const float*)d_in[1];
    const float* w_res      = (const float*)d_in[2];
    const float* w_pre      = (const float*)d_in[3];
    const float* w_post     = (const float*)d_in[4];
    const float* beta_res   = (const float*)d_in[5];
    const float* beta_pre   = (const float*)d_in[6];
    const float* beta_post  = (const float*)d_in[7];
    const float* alpha_res  = (const float*)d_in[8];
    const float* alpha_pre  = (const float*)d_in[9];
    const float* alpha_post = (const float*)d_in[10];

    const int nt = in_sizes[0] / KDIM;   // B*T tokens (8192)

    const int smem_bytes = 2 * RP * CK * 8 + 2 * TPB * CK * 4;  // 224 KB
    static bool attr_set = false;
    if (!attr_set) {
        cudaFuncSetAttribute(dots_kernel,
                             cudaFuncAttributeMaxDynamicSharedMemorySize,
                             smem_bytes);
        attr_set = true;
    }

    prep_kernel<<<(RP * KDIM + 255) / 256, 256>>>(w_res, w_pre, w_post, gamma);
    dots_kernel<<<nt / TPB, 256, smem_bytes>>>(residuals);
    heads_kernel<<<(nt + 127) / 128, 128>>>(beta_res, beta_pre, beta_post,
                                            alpha_res, alpha_pre, alpha_post, nt);
    mix_kernel<<<nt, 256>>>(residuals, (float*)d_out);
}

// round 8
// speedup vs baseline: 1.7333x; 1.1561x over previous
#include <cuda_runtime.h>
#include <math.h>
#include <stdint.h>

#define KDIM   4096
#define RROWS  24
#define MAXNT  8192

// ---- dots_mma geometry ----
#define MTOK   64                 // tokens per block
#define CKM    64                 // k per chunk
#define NCHM   (KDIM / CKM)       // 64 chunks
#define NBUFM  3
#define XROW   68                 // padded floats per smem row (bank-conflict-free)
#define XSZ    (MTOK * XROW * 4)  // 17408 B
#define WSZ    (RROWS * XROW * 4) // 6528 B
#define STGB   (XSZ + WSZ)        // 23936 B
#define SMEMM  (NBUFM * STGB)     // 71808 B

// -------- scratch (no cudaMalloc allowed) --------
__device__ float g_wN  [RROWS * KDIM];   // gamma-folded, tf32-rounded weights
__device__ float g_dots[MAXNT * RROWS];
__device__ float g_ssq [MAXNT];
__device__ float g_H   [MAXNT * RROWS];

// ---------------- helpers ----------------
__device__ __forceinline__ void cpasync16(void* dst_smem, const void* src) {
    unsigned d = (unsigned)__cvta_generic_to_shared(dst_smem);
    asm volatile("cp.async.cg.shared.global [%0], [%1], 16;" :: "r"(d), "l"(src));
}
__device__ __forceinline__ float ex2f(float x) {
    float r; asm("ex2.approx.f32 %0, %1;" : "=f"(r) : "f"(x)); return r;
}
__device__ __forceinline__ float lg2f(float x) {
    float r; asm("lg2.approx.f32 %0, %1;" : "=f"(r) : "f"(x)); return r;
}
__device__ __forceinline__ uint32_t tf32r(float f) {
    uint32_t r; asm("cvt.rna.tf32.f32 %0, %1;" : "=r"(r) : "f"(f)); return r;
}
__device__ __forceinline__ void mma8(float* c, uint32_t a0, uint32_t a1,
                                     uint32_t a2, uint32_t a3,
                                     uint32_t b0, uint32_t b1) {
    asm volatile(
        "mma.sync.aligned.m16n8k8.row.col.f32.tf32.tf32.f32 "
        "{%0,%1,%2,%3}, {%4,%5,%6,%7}, {%8,%9}, {%0,%1,%2,%3};"
        : "+f"(c[0]), "+f"(c[1]), "+f"(c[2]), "+f"(c[3])
        : "r"(a0), "r"(a1), "r"(a2), "r"(a3), "r"(b0), "r"(b1));
}

// ============================================================
// K0: fold gamma into weights, round to tf32 once
// ============================================================
__global__ void prep_kernel(const float* __restrict__ w_res,
                            const float* __restrict__ w_pre,
                            const float* __restrict__ w_post,
                            const float* __restrict__ gamma) {
    int idx = blockIdx.x * blockDim.x + threadIdx.x;
    if (idx >= RROWS * KDIM) return;
    int r = idx >> 12;
    int k = idx & (KDIM - 1);
    float w;
    if (r < 16)      w = w_res [r * KDIM + k];
    else if (r < 20) w = w_pre [(r - 16) * KDIM + k];
    else             w = w_post[(r - 20) * KDIM + k];
    g_wN[idx] = __uint_as_float(tf32r(w * (1.0f + gamma[k])));
}

// ============================================================
// K1: dots via mma.sync m16n8k8 tf32.
// Block = 64 tokens, 128 threads (4 warps); warp = 16 tokens x 24 rows
// (1 m-tile x 3 n-tiles). K chunked 64 at a time via cp.async (3 buffers).
// smem rows padded to 68 floats -> all fragment LDS conflict-free.
// ssq computed exactly (fp32) from the loaded A fragments for free.
// ============================================================
__global__ void __launch_bounds__(128, 2)
dots_mma(const float* __restrict__ x) {
    extern __shared__ __align__(16) char sm[];
    const int tid  = threadIdx.x;
    const int lane = tid & 31;
    const int warp = tid >> 5;            // 0..3
    const int g    = lane >> 2;           // group id 0..7
    const int tig  = lane & 3;            // thread in group
    const int tokb = blockIdx.x * MTOK;

#define STAGE(s) do {                                                          \
        if ((s) < NCHM) {                                                      \
            char* _b = sm + ((s) % NBUFM) * STGB;                              \
            const float* _xs = x + (size_t)tokb * KDIM + (s) * CKM;            \
            _Pragma("unroll")                                                  \
            for (int _j = 0; _j < 8; ++_j) {                                   \
                int _i = tid + 128 * _j;                                       \
                int _t = _i >> 4, _c = _i & 15;                                \
                cpasync16(_b + _t * (XROW * 4) + _c * 16,                      \
                          _xs + (size_t)_t * KDIM + _c * 4);                   \
            }                                                                  \
            _Pragma("unroll")                                                  \
            for (int _j = 0; _j < 3; ++_j) {                                   \
                int _i = tid + 128 * _j;                                       \
                int _t = _i >> 4, _c = _i & 15;                                \
                cpasync16(_b + XSZ + _t * (XROW * 4) + _c * 16,                \
                          g_wN + _t * KDIM + (s) * CKM + _c * 4);              \
            }                                                                  \
        }                                                                      \
        asm volatile("cp.async.commit_group;");                                \
    } while (0)

    float acc[3][4];
#pragma unroll
    for (int nt = 0; nt < 3; ++nt)
#pragma unroll
        for (int i = 0; i < 4; ++i) acc[nt][i] = 0.0f;
    float ssq0 = 0.0f, ssq1 = 0.0f;

    STAGE(0);
    STAGE(1);

    const int rowA0 = (warp * 16 + g) * XROW;
    const int rowA1 = rowA0 + 8 * XROW;

    for (int ch = 0; ch < NCHM; ++ch) {
        STAGE(ch + 2);
        asm volatile("cp.async.wait_group 2;" ::: "memory");
        __syncthreads();

        const float* xb = (const float*)(sm + (ch % NBUFM) * STGB);
        const float* wb = (const float*)(sm + (ch % NBUFM) * STGB + XSZ);

#pragma unroll
        for (int kt = 0; kt < 8; ++kt) {
            const int k0 = kt * 8 + tig;
            float a0f = xb[rowA0 + k0];
            float a1f = xb[rowA1 + k0];
            float a2f = xb[rowA0 + k0 + 4];
            float a3f = xb[rowA1 + k0 + 4];
            ssq0 = fmaf(a0f, a0f, fmaf(a2f, a2f, ssq0));
            ssq1 = fmaf(a1f, a1f, fmaf(a3f, a3f, ssq1));
            uint32_t A0 = tf32r(a0f), A1 = tf32r(a1f);
            uint32_t A2 = tf32r(a2f), A3 = tf32r(a3f);
#pragma unroll
            for (int nt = 0; nt < 3; ++nt) {
                uint32_t B0 = __float_as_uint(wb[(nt * 8 + g) * XROW + k0]);
                uint32_t B1 = __float_as_uint(wb[(nt * 8 + g) * XROW + k0 + 4]);
                mma8(acc[nt], A0, A1, A2, A3, B0, B1);
            }
        }
        __syncthreads();
    }

    // ---- epilogue: dots ----
    const int t0 = tokb + warp * 16 + g;
    const int t1 = t0 + 8;
#pragma unroll
    for (int nt = 0; nt < 3; ++nt) {
        int r = nt * 8 + 2 * tig;
        *(float2*)(g_dots + (size_t)t0 * RROWS + r) =
            make_float2(acc[nt][0], acc[nt][1]);
        *(float2*)(g_dots + (size_t)t1 * RROWS + r) =
            make_float2(acc[nt][2], acc[nt][3]);
    }

    // ---- ssq reduce across the 4-lane group ----
    ssq0 += __shfl_down_sync(0xffffffffu, ssq0, 2, 4);
    ssq0 += __shfl_down_sync(0xffffffffu, ssq0, 1, 4);
    ssq1 += __shfl_down_sync(0xffffffffu, ssq1, 2, 4);
    ssq1 += __shfl_down_sync(0xffffffffu, ssq1, 1, 4);
    if (tig == 0) {
        g_ssq[t0] = ssq0;
        g_ssq[t1] = ssq1;
    }
#undef STAGE
}

// ============================================================
// K2: per-token heads (sinkhorn + softmax + sigmoid), base-2 MUFU
// ============================================================
#define LOG2E 1.4426950408889634f

__device__ __forceinline__ float lse4_2(float a, float b, float c, float d) {
    float m = fmaxf(fmaxf(a, b), fmaxf(c, d));
    float s = ex2f(a - m) + ex2f(b - m) + ex2f(c - m) + ex2f(d - m);
    return m + lg2f(s);
}

__global__ void heads_kernel(const float* __restrict__ beta_res,
                             const float* __restrict__ beta_pre,
                             const float* __restrict__ beta_post,
                             const float* __restrict__ alpha_res,
                             const float* __restrict__ alpha_pre,
                             const float* __restrict__ alpha_post,
                             int nt) {
    int tok = blockIdx.x * blockDim.x + threadIdx.x;
    if (tok >= nt) return;

    float rstd = 64.0f / fmaxf(sqrtf(g_ssq[tok]), 1e-12f);
    const float* dp = g_dots + (size_t)tok * RROWS;
    float ar = alpha_res[0]  * rstd;
    float ap = alpha_pre[0]  * rstd;
    float ao = alpha_post[0] * rstd;

    float Z[16];
#pragma unroll
    for (int e = 0; e < 16; ++e)
        Z[e] = (beta_res[e] + ar * dp[e]) * (20.0f * LOG2E);

    float u[4] = {0.f, 0.f, 0.f, 0.f};
    float v[4] = {0.f, 0.f, 0.f, 0.f};
#pragma unroll 1
    for (int itn = 0; itn < 10; ++itn) {
#pragma unroll
        for (int i = 0; i < 4; ++i)
            u[i] = -lse4_2(Z[i*4+0] + v[0], Z[i*4+1] + v[1],
                           Z[i*4+2] + v[2], Z[i*4+3] + v[3]);
#pragma unroll
        for (int j = 0; j < 4; ++j)
            v[j] = -lse4_2(Z[0*4+j] + u[0], Z[1*4+j] + u[1],
                           Z[2*4+j] + u[2], Z[3*4+j] + u[3]);
    }

    float* hp = g_H + (size_t)tok * RROWS;
#pragma unroll
    for (int i = 0; i < 4; ++i)
#pragma unroll
        for (int j = 0; j < 4; ++j)
            hp[i*4+j] = ex2f(Z[i*4+j] + u[i] + v[j]);

    float p[4];
#pragma unroll
    for (int s = 0; s < 4; ++s)
        p[s] = (beta_pre[s] + ap * dp[16 + s]) * LOG2E;
    float m = fmaxf(fmaxf(p[0], p[1]), fmaxf(p[2], p[3]));
    float e0 = ex2f(p[0]-m), e1 = ex2f(p[1]-m);
    float e2 = ex2f(p[2]-m), e3 = ex2f(p[3]-m);
    float inv = 1.0f / (e0 + e1 + e2 + e3);
    hp[16] = e0*inv; hp[17] = e1*inv; hp[18] = e2*inv; hp[19] = e3*inv;

#pragma unroll
    for (int s = 0; s < 4; ++s) {
        float q = beta_post[s] + ao * dp[20 + s];
        hp[20 + s] = 2.0f / (1.0f + ex2f(-q * LOG2E));
    }
}

// ============================================================
// K3: out[i,d] = sum_j Hres[i][j] x[j,d] + Hpost[i] * sum_s Hpre[s] x[s,d]
// ============================================================
#define D4 1024
__global__ void __launch_bounds__(256)
mix_kernel(const float* __restrict__ x, float* __restrict__ out) {
    const int tok = blockIdx.x;
    const float* xr = x   + (size_t)tok * KDIM;
    float*       yr = out + (size_t)tok * KDIM;
    const float* hp = g_H + (size_t)tok * RROWS;

    float hres[16], hpre[4], hpost[4];
#pragma unroll
    for (int e = 0; e < 16; ++e) hres[e] = __ldg(hp + e);
#pragma unroll
    for (int s = 0; s < 4; ++s)  hpre[s]  = __ldg(hp + 16 + s);
#pragma unroll
    for (int s = 0; s < 4; ++s)  hpost[s] = __ldg(hp + 20 + s);

    const int col = threadIdx.x * 4;
    float4 xj[4];
#pragma unroll
    for (int j = 0; j < 4; ++j)
        xj[j] = __ldcs((const float4*)(xr + j * D4 + col));

    float4 bin;
    bin.x = hpre[0]*xj[0].x + hpre[1]*xj[1].x + hpre[2]*xj[2].x + hpre[3]*xj[3].x;
    bin.y = hpre[0]*xj[0].y + hpre[1]*xj[1].y + hpre[2]*xj[2].y + hpre[3]*xj[3].y;
    bin.z = hpre[0]*xj[0].z + hpre[1]*xj[1].z + hpre[2]*xj[2].z + hpre[3]*xj[3].z;
    bin.w = hpre[0]*xj[0].w + hpre[1]*xj[1].w + hpre[2]*xj[2].w + hpre[3]*xj[3].w;

#pragma unroll
    for (int i = 0; i < 4; ++i) {
        float4 o;
        o.x = hpost[i]*bin.x; o.y = hpost[i]*bin.y;
        o.z = hpost[i]*bin.z; o.w = hpost[i]*bin.w;
#pragma unroll
        for (int j = 0; j < 4; ++j) {
            float h = hres[i*4 + j];
            o.x += h * xj[j].x; o.y += h * xj[j].y;
            o.z += h * xj[j].z; o.w += h * xj[j].w;
        }
        __stcs((float4*)(yr + i * D4 + col), o);
    }
}

// ============================================================
// launch
// ============================================================
extern "C" void kernel_launch(void* const* d_in, const int* in_sizes, int n_in,
                              void* d_out, int out_size) {
    const float* residuals  = (const float*)d_in[0];
    const float* gamma      = (const float*)d_in[1];
    const float* w_res      = (const float*)d_in[2];
    const float* w_pre      = (const float*)d_in[3];
    const float* w_post     = (const float*)d_in[4];
    const float* beta_res   = (const float*)d_in[5];
    const float* beta_pre   = (const float*)d_in[6];
    const float* beta_post  = (const float*)d_in[7];
    const float* alpha_res  = (const float*)d_in[8];
    const float* alpha_pre  = (const float*)d_in[9];
    const float* alpha_post = (const float*)d_in[10];

    const int nt = in_sizes[0] / KDIM;   // B*T tokens (8192)

    static bool attr_set = false;
    if (!attr_set) {
        cudaFuncSetAttribute(dots_mma,
                             cudaFuncAttributeMaxDynamicSharedMemorySize,
                             SMEMM);
        attr_set = true;
    }

    prep_kernel<<<(RROWS * KDIM + 255) / 256, 256>>>(w_res, w_pre, w_post, gamma);
    dots_mma<<<nt / MTOK, 128, SMEMM>>>(residuals);
    heads_kernel<<<(nt + 127) / 128, 128>>>(beta_res, beta_pre, beta_post,
                                            alpha_res, alpha_pre, alpha_post, nt);
    mix_kernel<<<nt, 256>>>(residuals, (float*)d_out);
}